// round 7
// baseline (speedup 1.0000x reference)
#include <cuda_runtime.h>
#include <cuda_fp16.h>

#define NN 100000
#define EE 1600000
#define C  64

#define SCAN_B 512
#define SCAN_NB ((NN + SCAN_B - 1) / SCAN_B)   // 196

// padded CSR capacity: every node segment rounded up to even
#define ECAP (EE + 2 * NN + 64)

// ---- scratch (device globals: no allocation allowed) ----
__device__ int       g_deg[NN];               // in-degree histogram (self loop NOT included)
__device__ int       g_off[NN];               // padded-even offsets
__device__ int       g_cur[NN];
__device__ float     g_dis[NN];
__device__ int       g_bsum[SCAN_NB];
__device__ int       g_boff[SCAN_NB];
__device__ int2      g_edge[ECAP];            // (src, dis[src] bits), even-aligned segments
__device__ unsigned  g_xwh[(size_t)NN * 32];  // X@W, half2-packed: [row*32+l] = (col 2l, 2l+1)
__device__ float     g_x [(size_t)NN * C];    // layer activations (fp32)
__device__ double    g_stats[2];              // sum, sumsq

// ---------------- zero histogram ----------------
__global__ void k_hist_init() {
    int i = blockIdx.x * blockDim.x + threadIdx.x;
    if (i < NN) g_deg[i] = 0;
}
__global__ void k_hist(const int* __restrict__ dst) {
    int stride = gridDim.x * blockDim.x;
    for (int e = blockIdx.x * blockDim.x + threadIdx.x; e < EE; e += stride)
        atomicAdd(&g_deg[dst[e]], 1);
}

// ---------------- scan A: block-local exclusive scan of padded counts ----------------
__global__ void k_scan_a() {
    __shared__ int sh[SCAN_B];
    int t = threadIdx.x;
    int i = blockIdx.x * SCAN_B + t;
    int v = (i < NN) ? ((g_deg[i] + 2) & ~1) : 0;   // (deg+1 self loop) rounded up to even
    sh[t] = v;
    __syncthreads();
    int acc = v;
#pragma unroll
    for (int d = 1; d < SCAN_B; d <<= 1) {
        int u = (t >= d) ? sh[t - d] : 0;
        __syncthreads();
        acc += u;
        sh[t] = acc;
        __syncthreads();
    }
    if (i < NN) g_off[i] = acc - v;            // local exclusive
    if (t == SCAN_B - 1) g_bsum[blockIdx.x] = acc;
}

// ---------------- scan B: exclusive scan of block totals + zero stats ----------------
__global__ void k_scan_b() {
    __shared__ int sh[256];
    int t = threadIdx.x;
    if (t < 2) g_stats[t] = 0.0;
    int v = (t < SCAN_NB) ? g_bsum[t] : 0;
    sh[t] = v;
    __syncthreads();
    int acc = v;
#pragma unroll
    for (int d = 1; d < 256; d <<= 1) {
        int u = (t >= d) ? sh[t - d] : 0;
        __syncthreads();
        acc += u;
        sh[t] = acc;
        __syncthreads();
    }
    if (t < SCAN_NB) g_boff[t] = acc - v;
}

// ---------------- scan C: global offsets, cur, dis = rsqrt(deg+1) ----------------
__global__ void k_scan_c() {
    int i = blockIdx.x * blockDim.x + threadIdx.x;
    if (i >= NN) return;
    int off = g_off[i] + g_boff[i / SCAN_B];
    g_off[i] = off;
    g_cur[i] = off;
    g_dis[i] = rsqrtf((float)(g_deg[i] + 1));
}

// ---------------- fill CSR (edges + self loops), packed (src, w) ----------------
__global__ void k_fill(const int* __restrict__ src,
                       const int* __restrict__ dst) {
    int stride = gridDim.x * blockDim.x;
    const int tot = EE + NN;
    for (int e = blockIdx.x * blockDim.x + threadIdx.x; e < tot; e += stride) {
        int s, d;
        if (e < EE) { s = src[e]; d = dst[e]; }
        else        { s = e - EE; d = s; }
        int pos = atomicAdd(&g_cur[d], 1);
        float w = g_dis[s];
        g_edge[pos] = make_int2(s, __float_as_int(w));
    }
}

// ---------------- GEMM: g_xwh = half2(in @ W), 4 rows/warp, shuffle-free ----------------
#define RPW 4
__global__ void k_gemm(const float* __restrict__ Xin,
                       const float* __restrict__ W,
                       int from_global) {
    __shared__ float2 Wp[C][32];    // Wp[k][l] = (W[k][2l], W[k][2l+1])
    __shared__ float4 Xs[8][C];     // Xs[warp][k] = x of 4 rows at col k
    for (int i = threadIdx.x; i < C * 32; i += blockDim.x) {
        int k = i >> 5, l = i & 31;
        Wp[k][l] = make_float2(W[k * C + 2 * l], W[k * C + 2 * l + 1]);
    }

    int warp = (blockIdx.x * blockDim.x + threadIdx.x) >> 5;
    int w    = (threadIdx.x >> 5);
    int lane = threadIdx.x & 31;
    bool live = (warp < NN / RPW);

    const float* base = from_global ? g_x : Xin;
    int r0 = warp * RPW;

    if (live) {
        // lane l holds cols (2l, 2l+1) of the warp's 4 rows; transpose into Xs
        float2 xv[RPW];
#pragma unroll
        for (int i = 0; i < RPW; i++)
            xv[i] = *(const float2*)(base + (size_t)(r0 + i) * C + 2 * lane);
        Xs[w][2 * lane]     = make_float4(xv[0].x, xv[1].x, xv[2].x, xv[3].x);
        Xs[w][2 * lane + 1] = make_float4(xv[0].y, xv[1].y, xv[2].y, xv[3].y);
    }
    __syncthreads();
    if (!live) return;

    float a0[RPW] = {0.f, 0.f, 0.f, 0.f};
    float a1[RPW] = {0.f, 0.f, 0.f, 0.f};
#pragma unroll
    for (int k = 0; k < C; k++) {
        float4 xk = Xs[w][k];          // uniform -> LDS.128 broadcast
        float2 wv = Wp[k][lane];       // LDS.64, conflict-free
        a0[0] += xk.x * wv.x;  a1[0] += xk.x * wv.y;
        a0[1] += xk.y * wv.x;  a1[1] += xk.y * wv.y;
        a0[2] += xk.z * wv.x;  a1[2] += xk.z * wv.y;
        a0[3] += xk.w * wv.x;  a1[3] += xk.w * wv.y;
    }
#pragma unroll
    for (int i = 0; i < RPW; i++) {
        __half2 h = __float22half2_rn(make_float2(a0[i], a1[i]));
        g_xwh[(size_t)(r0 + i) * 32 + lane] = *(unsigned*)&h;
    }
}

// ---------------- aggregate: warp/node, int4 edge loads, 32-deep gather ----------------
__global__ void __launch_bounds__(256, 2)
k_agg(const float* __restrict__ bias) {
    int node = (blockIdx.x * blockDim.x + threadIdx.x) >> 5;
    int lane = threadIdx.x & 31;
    if (node >= NN) return;

    int   off = g_off[node];               // even
    int   cnt = g_deg[node] + 1;
    float di  = g_dis[node];
    float ax = 0.f, ay = 0.f;

    const int4* e4 = (const int4*)g_edge;  // 2 edges per int4
    int b4 = off >> 1;

    for (int t0 = 0; t0 < cnt; t0 += 32, b4 += 16) {
        // group A: edges t0..t0+15
        int4 eb[8];
#pragma unroll
        for (int j = 0; j < 8; j++) eb[j] = e4[b4 + j];       // uniform LDG.128
        unsigned hv[16]; float ww[16];
#pragma unroll
        for (int j = 0; j < 16; j++) {
            int4 p = eb[j >> 1];
            int   s = (j & 1) ? p.z : p.x;
            int   wb= (j & 1) ? p.w : p.y;
            bool ok = (t0 + j < cnt);                          // warp-uniform
            ww[j] = ok ? __int_as_float(wb) : 0.f;
            hv[j] = g_xwh[(size_t)(ok ? s : 0) * 32 + lane];
        }

        bool haveB = (t0 + 16) < cnt;                          // warp-uniform
        unsigned hv2[16]; float ww2[16];
        if (haveB) {
            int4 eb2[8];
#pragma unroll
            for (int j = 0; j < 8; j++) eb2[j] = e4[b4 + 8 + j];
#pragma unroll
            for (int j = 0; j < 16; j++) {
                int4 p = eb2[j >> 1];
                int   s = (j & 1) ? p.z : p.x;
                int   wb= (j & 1) ? p.w : p.y;
                bool ok = (t0 + 16 + j < cnt);
                ww2[j] = ok ? __int_as_float(wb) : 0.f;
                hv2[j] = g_xwh[(size_t)(ok ? s : 0) * 32 + lane];
            }
        }

#pragma unroll
        for (int j = 0; j < 16; j++) {
            float2 v = __half22float2(*(__half2*)&hv[j]);
            ax += ww[j] * v.x;
            ay += ww[j] * v.y;
        }
        if (haveB) {
#pragma unroll
            for (int j = 0; j < 16; j++) {
                float2 v = __half22float2(*(__half2*)&hv2[j]);
                ax += ww2[j] * v.x;
                ay += ww2[j] * v.y;
            }
        }
    }

    float2 b = *(const float2*)(bias + 2 * lane);
    float o0 = fmaxf(ax * di + b.x, 0.f);
    float o1 = fmaxf(ay * di + b.y, 0.f);
    *(float2*)(g_x + (size_t)node * C + 2 * lane) = make_float2(o0, o1);
}

// ---------------- global sum / sumsq over g_x ----------------
__global__ void k_reduce() {
    const int M = NN * C;
    float s = 0.f, s2 = 0.f;
    int stride = gridDim.x * blockDim.x;
    for (int i = blockIdx.x * blockDim.x + threadIdx.x; i < M; i += stride) {
        float v = g_x[i];
        s  += v;
        s2 += v * v;
    }
#pragma unroll
    for (int o = 16; o; o >>= 1) {
        s  += __shfl_down_sync(0xffffffffu, s,  o);
        s2 += __shfl_down_sync(0xffffffffu, s2, o);
    }
    __shared__ float ss[32], ss2[32];
    int lane = threadIdx.x & 31, w = threadIdx.x >> 5;
    if (lane == 0) { ss[w] = s; ss2[w] = s2; }
    __syncthreads();
    if (w == 0) {
        int nw = blockDim.x >> 5;
        s  = (lane < nw) ? ss[lane]  : 0.f;
        s2 = (lane < nw) ? ss2[lane] : 0.f;
#pragma unroll
        for (int o = 16; o; o >>= 1) {
            s  += __shfl_down_sync(0xffffffffu, s,  o);
            s2 += __shfl_down_sync(0xffffffffu, s2, o);
        }
        if (lane == 0) {
            atomicAdd(&g_stats[0], (double)s);
            atomicAdd(&g_stats[1], (double)s2);
        }
    }
}

// ---------------- graph layernorm ----------------
__global__ void k_ln(const float* __restrict__ lnw,
                     const float* __restrict__ lnb,
                     float* __restrict__ out) {
    const int M = NN * C;
    double mean = g_stats[0] / (double)M;
    double var  = g_stats[1] / (double)M - mean * mean;
    float scale = (float)(1.0 / sqrt(var + 1e-5)) * lnw[0];
    float mu    = (float)mean;
    float shb   = lnb[0];
    int stride = gridDim.x * blockDim.x;
    for (int i = blockIdx.x * blockDim.x + threadIdx.x; i < M; i += stride)
        out[i] = (g_x[i] - mu) * scale + shb;
}

extern "C" void kernel_launch(void* const* d_in, const int* in_sizes, int n_in,
                              void* d_out, int out_size) {
    const float* X    = (const float*)d_in[0];
    const int*   edges= (const int*)d_in[1];   // int32 (JAX x64 disabled)
    const float* W1   = (const float*)d_in[2];
    const float* b1   = (const float*)d_in[3];
    const float* W2   = (const float*)d_in[4];
    const float* b2   = (const float*)d_in[5];
    const float* lnw  = (const float*)d_in[6];
    const float* lnb  = (const float*)d_in[7];
    float* out = (float*)d_out;

    const int* srcp = edges;        // edges[0]
    const int* dstp = edges + EE;   // edges[1]

    const int agg_grid  = (NN * 32 + 255) / 256;           // warp per node
    const int gemm_grid = ((NN / RPW) * 32 + 255) / 256;   // 4 rows per warp

    k_hist_init<<<(NN + 255) / 256, 256>>>();
    k_hist<<<2048, 256>>>(dstp);
    k_scan_a<<<SCAN_NB, SCAN_B>>>();
    k_gemm<<<gemm_grid, 256>>>(X, W1, 0);      // slot 3: gets ncu-sampled
    k_scan_b<<<1, 256>>>();
    k_scan_c<<<(NN + 255) / 256, 256>>>();
    k_fill<<<2048, 256>>>(srcp, dstp);

    // layer 1 aggregation
    k_agg<<<agg_grid, 256>>>(b1);
    // layer 2 (residual mix GW*h+(1-GW)*h == h)
    k_gemm<<<gemm_grid, 256>>>(X, W2, 1);
    k_agg<<<agg_grid, 256>>>(b2);

    // graph layernorm
    k_reduce<<<1024, 256>>>();
    k_ln<<<4096, 256>>>(lnw, lnb, out);
}

// round 8
// speedup vs baseline: 1.1775x; 1.1775x over previous
#include <cuda_runtime.h>
#include <cuda_fp16.h>

#define NN 100000
#define EE 1600000
#define C  64
#define TOT (EE + NN)

#define SCAN_B 512
#define SCAN_NB ((NN + SCAN_B - 1) / SCAN_B)   // 196

// ---- scratch (device globals: no allocation allowed) ----
__device__ int       g_deg[NN];               // in-degree histogram (self loop NOT included)
__device__ int       g_off[NN];
__device__ int       g_cur[NN];
__device__ float     g_dis[NN];
__device__ int       g_bsum[SCAN_NB];
__device__ int       g_boff[SCAN_NB];
__device__ int2      g_edge[TOT + 32];        // (src, dis[src] bits), padded for prefetch overrun
__device__ unsigned  g_xwh[(size_t)NN * 32];  // X@W, half2-packed: [row*32+l] = (col 2l, 2l+1)
__device__ float     g_x [(size_t)NN * C];    // layer activations (fp32)
__device__ double    g_stats[2];              // sum, sumsq

// ---------------- zero histogram ----------------
__global__ void k_hist_init() {
    int i = blockIdx.x * blockDim.x + threadIdx.x;
    if (i < NN) g_deg[i] = 0;
}
__global__ void k_hist(const int* __restrict__ dst) {
    int stride = gridDim.x * blockDim.x;
    for (int e = blockIdx.x * blockDim.x + threadIdx.x; e < EE; e += stride)
        atomicAdd(&g_deg[dst[e]], 1);
}

// ---------------- scan A: block-local exclusive scan of (deg+1) ----------------
__global__ void k_scan_a() {
    __shared__ int sh[SCAN_B];
    int t = threadIdx.x;
    int i = blockIdx.x * SCAN_B + t;
    int v = (i < NN) ? (g_deg[i] + 1) : 0;
    sh[t] = v;
    __syncthreads();
    int acc = v;
#pragma unroll
    for (int d = 1; d < SCAN_B; d <<= 1) {
        int u = (t >= d) ? sh[t - d] : 0;
        __syncthreads();
        acc += u;
        sh[t] = acc;
        __syncthreads();
    }
    if (i < NN) g_off[i] = acc - v;            // local exclusive
    if (t == SCAN_B - 1) g_bsum[blockIdx.x] = acc;
}

// ---------------- scan B: exclusive scan of block totals + zero stats ----------------
__global__ void k_scan_b() {
    __shared__ int sh[256];
    int t = threadIdx.x;
    if (t < 2) g_stats[t] = 0.0;
    int v = (t < SCAN_NB) ? g_bsum[t] : 0;
    sh[t] = v;
    __syncthreads();
    int acc = v;
#pragma unroll
    for (int d = 1; d < 256; d <<= 1) {
        int u = (t >= d) ? sh[t - d] : 0;
        __syncthreads();
        acc += u;
        sh[t] = acc;
        __syncthreads();
    }
    if (t < SCAN_NB) g_boff[t] = acc - v;
}

// ---------------- scan C: global offsets, cur, dis = rsqrt(deg+1) ----------------
__global__ void k_scan_c() {
    int i = blockIdx.x * blockDim.x + threadIdx.x;
    if (i >= NN) return;
    int off = g_off[i] + g_boff[i / SCAN_B];
    g_off[i] = off;
    g_cur[i] = off;
    g_dis[i] = rsqrtf((float)(g_deg[i] + 1));
}

// ---------------- fill CSR (edges + self loops), packed (src, w) ----------------
__global__ void k_fill(const int* __restrict__ src,
                       const int* __restrict__ dst) {
    int stride = gridDim.x * blockDim.x;
    for (int e = blockIdx.x * blockDim.x + threadIdx.x; e < TOT; e += stride) {
        int s, d;
        if (e < EE) { s = src[e]; d = dst[e]; }
        else        { s = e - EE; d = s; }
        int pos = atomicAdd(&g_cur[d], 1);
        float w = g_dis[s];
        g_edge[pos] = make_int2(s, __float_as_int(w));
    }
}

// ---------------- GEMM: g_xwh = half2(in @ W), 4 rows/warp, shuffle-free ----------------
#define RPW 4
__global__ void k_gemm(const float* __restrict__ Xin,
                       const float* __restrict__ W,
                       int from_global) {
    __shared__ float2 Wp[C][32];    // Wp[k][l] = (W[k][2l], W[k][2l+1])
    __shared__ float4 Xs[8][C];     // Xs[warp][k] = x of 4 rows at col k
    for (int i = threadIdx.x; i < C * 32; i += blockDim.x) {
        int k = i >> 5, l = i & 31;
        Wp[k][l] = make_float2(W[k * C + 2 * l], W[k * C + 2 * l + 1]);
    }

    int warp = (blockIdx.x * blockDim.x + threadIdx.x) >> 5;
    int w    = (threadIdx.x >> 5);
    int lane = threadIdx.x & 31;
    bool live = (warp < NN / RPW);

    const float* base = from_global ? g_x : Xin;
    int r0 = warp * RPW;

    if (live) {
        float2 xv[RPW];
#pragma unroll
        for (int i = 0; i < RPW; i++)
            xv[i] = *(const float2*)(base + (size_t)(r0 + i) * C + 2 * lane);
        Xs[w][2 * lane]     = make_float4(xv[0].x, xv[1].x, xv[2].x, xv[3].x);
        Xs[w][2 * lane + 1] = make_float4(xv[0].y, xv[1].y, xv[2].y, xv[3].y);
    }
    __syncthreads();
    if (!live) return;

    float a0[RPW] = {0.f, 0.f, 0.f, 0.f};
    float a1[RPW] = {0.f, 0.f, 0.f, 0.f};
#pragma unroll
    for (int k = 0; k < C; k++) {
        float4 xk = Xs[w][k];          // uniform -> LDS.128 broadcast
        float2 wv = Wp[k][lane];       // LDS.64, conflict-free
        a0[0] += xk.x * wv.x;  a1[0] += xk.x * wv.y;
        a0[1] += xk.y * wv.x;  a1[1] += xk.y * wv.y;
        a0[2] += xk.z * wv.x;  a1[2] += xk.z * wv.y;
        a0[3] += xk.w * wv.x;  a1[3] += xk.w * wv.y;
    }
#pragma unroll
    for (int i = 0; i < RPW; i++) {
        __half2 h = __float22half2_rn(make_float2(a0[i], a1[i]));
        g_xwh[(size_t)(r0 + i) * 32 + lane] = *(unsigned*)&h;
    }
}

// ---------------- aggregate (R6 form): warp/node, shuffle-free uniform edge broadcast,
//                  16-deep pipelined batches; optional fused global stats ----------------
// NOTE: grid is exactly NN warps (12500 blocks x 8 warps) -> no early-return warps,
// so __syncthreads in the fused-stats epilogue is safe.
__global__ void k_agg(const float* __restrict__ bias, int do_stats) {
    int node = (blockIdx.x * blockDim.x + threadIdx.x) >> 5;
    int lane = threadIdx.x & 31;

    int   off = g_off[node];
    int   cnt = g_deg[node] + 1;
    float di  = g_dis[node];
    float ax = 0.f, ay = 0.f;

    // prefetch first edge batch (uniform broadcast loads; padded array makes overrun safe)
    int2 e[16];
#pragma unroll
    for (int j = 0; j < 16; j++) e[j] = g_edge[off + j];

    for (int t0 = 0; t0 < cnt; t0 += 16) {
        // prefetch next batch (hides edge-load latency behind this batch's work)
        int2 en[16];
        int nb = off + t0 + 16;
#pragma unroll
        for (int j = 0; j < 16; j++) en[j] = g_edge[nb + j];

        // feature gathers (unconditional; masked rows -> row 0 with weight 0)
        unsigned hv[16]; float ww[16];
#pragma unroll
        for (int j = 0; j < 16; j++) {
            bool ok  = (t0 + j < cnt);               // warp-uniform
            int  row = ok ? e[j].x : 0;
            ww[j]    = ok ? __int_as_float(e[j].y) : 0.f;
            hv[j]    = g_xwh[(size_t)row * 32 + lane];
        }
#pragma unroll
        for (int j = 0; j < 16; j++) {
            float2 v = __half22float2(*(__half2*)&hv[j]);
            ax += ww[j] * v.x;
            ay += ww[j] * v.y;
        }
#pragma unroll
        for (int j = 0; j < 16; j++) e[j] = en[j];
    }

    float2 b = *(const float2*)(bias + 2 * lane);
    float o0 = fmaxf(ax * di + b.x, 0.f);
    float o1 = fmaxf(ay * di + b.y, 0.f);
    *(float2*)(g_x + (size_t)node * C + 2 * lane) = make_float2(o0, o1);

    if (do_stats) {
        float s  = o0 + o1;
        float s2 = o0 * o0 + o1 * o1;
#pragma unroll
        for (int o = 16; o; o >>= 1) {
            s  += __shfl_down_sync(0xffffffffu, s,  o);
            s2 += __shfl_down_sync(0xffffffffu, s2, o);
        }
        __shared__ float ss[8], ss2[8];
        int w = threadIdx.x >> 5;
        if (lane == 0) { ss[w] = s; ss2[w] = s2; }
        __syncthreads();
        if (w == 0 && lane < 8) {
            s  = ss[lane];
            s2 = ss2[lane];
#pragma unroll
            for (int o = 4; o; o >>= 1) {
                s  += __shfl_down_sync(0x000000ffu, s,  o);
                s2 += __shfl_down_sync(0x000000ffu, s2, o);
            }
            if (lane == 0) {
                atomicAdd(&g_stats[0], (double)s);
                atomicAdd(&g_stats[1], (double)s2);
            }
        }
    }
}

// ---------------- graph layernorm ----------------
__global__ void k_ln(const float* __restrict__ lnw,
                     const float* __restrict__ lnb,
                     float* __restrict__ out) {
    const int M = NN * C;
    double mean = g_stats[0] / (double)M;
    double var  = g_stats[1] / (double)M - mean * mean;
    float scale = (float)(1.0 / sqrt(var + 1e-5)) * lnw[0];
    float mu    = (float)mean;
    float shb   = lnb[0];
    int stride = gridDim.x * blockDim.x;
    for (int i = blockIdx.x * blockDim.x + threadIdx.x; i < M; i += stride)
        out[i] = (g_x[i] - mu) * scale + shb;
}

extern "C" void kernel_launch(void* const* d_in, const int* in_sizes, int n_in,
                              void* d_out, int out_size) {
    const float* X    = (const float*)d_in[0];
    const int*   edges= (const int*)d_in[1];   // int32 (JAX x64 disabled)
    const float* W1   = (const float*)d_in[2];
    const float* b1   = (const float*)d_in[3];
    const float* W2   = (const float*)d_in[4];
    const float* b2   = (const float*)d_in[5];
    const float* lnw  = (const float*)d_in[6];
    const float* lnb  = (const float*)d_in[7];
    float* out = (float*)d_out;

    const int* srcp = edges;        // edges[0]
    const int* dstp = edges + EE;   // edges[1]

    const int agg_grid  = (NN * 32) / 256;                 // exactly 12500, no tail
    const int gemm_grid = ((NN / RPW) * 32 + 255) / 256;   // 4 rows per warp

    k_hist_init<<<(NN + 255) / 256, 256>>>();
    k_hist<<<2048, 256>>>(dstp);
    k_scan_a<<<SCAN_NB, SCAN_B>>>();
    k_gemm<<<gemm_grid, 256>>>(X, W1, 0);      // slot 3: gets ncu-sampled (control)
    k_scan_b<<<1, 256>>>();
    k_scan_c<<<(NN + 255) / 256, 256>>>();
    k_fill<<<2048, 256>>>(srcp, dstp);

    // layer 1 aggregation
    k_agg<<<agg_grid, 256>>>(b1, 0);
    // layer 2 (residual mix GW*h+(1-GW)*h == h); agg2 fuses global stats
    k_gemm<<<gemm_grid, 256>>>(X, W2, 1);
    k_agg<<<agg_grid, 256>>>(b2, 1);

    // graph layernorm
    k_ln<<<4096, 256>>>(lnw, lnb, out);
}

// round 9
// speedup vs baseline: 1.2880x; 1.0938x over previous
#include <cuda_runtime.h>
#include <cuda_fp16.h>

#define NN 100000
#define EE 1600000
#define C  64

#define SCAN_B 512
#define SCAN_NB ((NN + SCAN_B - 1) / SCAN_B)   // 196

// padded CSR: every node segment rounded up to multiple of 16 edges
#define ECAP_E (EE + 16 * NN)        // 3.2M int2 upper bound
#define ECAP_4 (ECAP_E / 2)          // int4 count

// ---- scratch (device globals: no allocation allowed) ----
__device__ int       g_deg[NN];               // in-degree (self loop NOT included)
__device__ int       g_off[NN];               // padded offsets (multiple of 16)
__device__ int       g_cur[NN];
__device__ float     g_dis[NN];
__device__ int       g_bsum[SCAN_NB];
__device__ int       g_boff[SCAN_NB];
__device__ int4      g_edge4[ECAP_4];         // (src*32, w_bits) pairs, 16B aligned
__device__ unsigned  g_xwh[(size_t)NN * 32];  // X@W, half2-packed: [row*32+l] = (col 2l, 2l+1)
__device__ float     g_x [(size_t)NN * C];    // layer activations (fp32)
__device__ double    g_stats[2];              // sum, sumsq

#define FMA2(acc, a, b) \
    asm("fma.rn.f32x2 %0, %1, %2, %0;" : "+l"(acc) : "l"(a), "l"(b))
#define UNPK(lo, hi, v) \
    asm("mov.b64 {%0, %1}, %2;" : "=f"(lo), "=f"(hi) : "l"(v))

// ---------------- clear: edge pad slots, histogram, stats ----------------
__global__ void k_clear() {
    int i = blockIdx.x * blockDim.x + threadIdx.x;
    int stride = gridDim.x * blockDim.x;
    for (int j = i; j < ECAP_4; j += stride)
        g_edge4[j] = make_int4(0, 0, 0, 0);
    if (i < NN) g_deg[i] = 0;
    if (i < 2)  g_stats[i] = 0.0;
}

__global__ void k_hist(const int* __restrict__ dst) {
    int stride = gridDim.x * blockDim.x;
    for (int e = blockIdx.x * blockDim.x + threadIdx.x; e < EE; e += stride)
        atomicAdd(&g_deg[dst[e]], 1);
}

// ---------------- scan A: block-local exclusive scan of pad16(deg+1) ----------------
__global__ void k_scan_a() {
    __shared__ int sh[SCAN_B];
    int t = threadIdx.x;
    int i = blockIdx.x * SCAN_B + t;
    int v = (i < NN) ? ((g_deg[i] + 16) & ~15) : 0;
    sh[t] = v;
    __syncthreads();
    int acc = v;
#pragma unroll
    for (int d = 1; d < SCAN_B; d <<= 1) {
        int u = (t >= d) ? sh[t - d] : 0;
        __syncthreads();
        acc += u;
        sh[t] = acc;
        __syncthreads();
    }
    if (i < NN) g_off[i] = acc - v;            // local exclusive
    if (t == SCAN_B - 1) g_bsum[blockIdx.x] = acc;
}

// ---------------- scan B: exclusive scan of block totals ----------------
__global__ void k_scan_b() {
    __shared__ int sh[256];
    int t = threadIdx.x;
    int v = (t < SCAN_NB) ? g_bsum[t] : 0;
    sh[t] = v;
    __syncthreads();
    int acc = v;
#pragma unroll
    for (int d = 1; d < 256; d <<= 1) {
        int u = (t >= d) ? sh[t - d] : 0;
        __syncthreads();
        acc += u;
        sh[t] = acc;
        __syncthreads();
    }
    if (t < SCAN_NB) g_boff[t] = acc - v;
}

// ---------------- scan C: global offsets, cur, dis = rsqrt(deg+1) ----------------
__global__ void k_scan_c() {
    int i = blockIdx.x * blockDim.x + threadIdx.x;
    if (i >= NN) return;
    int off = g_off[i] + g_boff[i / SCAN_B];
    g_off[i] = off;
    g_cur[i] = off;
    g_dis[i] = rsqrtf((float)(g_deg[i] + 1));
}

// ---------------- fill CSR (edges + self loops): (src*32, w_bits) ----------------
__global__ void k_fill(const int* __restrict__ src,
                       const int* __restrict__ dst) {
    int stride = gridDim.x * blockDim.x;
    const int tot = EE + NN;
    int2* ge = (int2*)g_edge4;
    for (int e = blockIdx.x * blockDim.x + threadIdx.x; e < tot; e += stride) {
        int s, d;
        if (e < EE) { s = src[e]; d = dst[e]; }
        else        { s = e - EE; d = s; }
        int pos = atomicAdd(&g_cur[d], 1);
        float w = g_dis[s];
        ge[pos] = make_int2(s * 32, __float_as_int(w));
    }
}

// ---------------- GEMM: g_xwh = half2(in @ W), 4 rows/warp, FFMA2 ----------------
#define RPW 4
__global__ void k_gemm(const float* __restrict__ Xin,
                       const float* __restrict__ W,
                       int from_global) {
    __shared__ float4 Wq[C][32];    // (wx, wx, wy, wy) for cols (2l, 2l+1)
    __shared__ float4 Xs[8][C];     // Xs[warp][k] = x of the warp's 4 rows at col k
    for (int i = threadIdx.x; i < C * 32; i += blockDim.x) {
        int k = i >> 5, l = i & 31;
        float wx = W[k * C + 2 * l];
        float wy = W[k * C + 2 * l + 1];
        Wq[k][l] = make_float4(wx, wx, wy, wy);
    }

    int warp = (blockIdx.x * blockDim.x + threadIdx.x) >> 5;   // < NN/RPW exactly
    int w    = (threadIdx.x >> 5);
    int lane = threadIdx.x & 31;

    const float* base = from_global ? g_x : Xin;
    int r0 = warp * RPW;

    {
        float2 xv[RPW];
#pragma unroll
        for (int i = 0; i < RPW; i++)
            xv[i] = *(const float2*)(base + (size_t)(r0 + i) * C + 2 * lane);
        Xs[w][2 * lane]     = make_float4(xv[0].x, xv[1].x, xv[2].x, xv[3].x);
        Xs[w][2 * lane + 1] = make_float4(xv[0].y, xv[1].y, xv[2].y, xv[3].y);
    }
    __syncthreads();

    unsigned long long A0l = 0ull, A0h = 0ull, A1l = 0ull, A1h = 0ull;
#pragma unroll
    for (int k = 0; k < C; k++) {
        ulonglong2 xp = *reinterpret_cast<const ulonglong2*>(&Xs[w][k]);   // (r0,r1),(r2,r3)
        ulonglong2 wp = *reinterpret_cast<const ulonglong2*>(&Wq[k][lane]); // (wx,wx),(wy,wy)
        FMA2(A0l, xp.x, wp.x);
        FMA2(A0h, xp.y, wp.x);
        FMA2(A1l, xp.x, wp.y);
        FMA2(A1h, xp.y, wp.y);
    }
    float a00, a01, a02, a03, a10, a11, a12, a13;
    UNPK(a00, a01, A0l);   // a0 of rows 0,1
    UNPK(a02, a03, A0h);   // a0 of rows 2,3
    UNPK(a10, a11, A1l);   // a1 of rows 0,1
    UNPK(a12, a13, A1h);   // a1 of rows 2,3

    __half2 h;
    h = __floats2half2_rn(a00, a10); g_xwh[(size_t)(r0 + 0) * 32 + lane] = *(unsigned*)&h;
    h = __floats2half2_rn(a01, a11); g_xwh[(size_t)(r0 + 1) * 32 + lane] = *(unsigned*)&h;
    h = __floats2half2_rn(a02, a12); g_xwh[(size_t)(r0 + 2) * 32 + lane] = *(unsigned*)&h;
    h = __floats2half2_rn(a03, a13); g_xwh[(size_t)(r0 + 3) * 32 + lane] = *(unsigned*)&h;
}

// ---------------- aggregate: warp/node, padded unconditional 16-edge batches ----------------
// grid exactly NN warps -> no early-out; __syncthreads in stats epilogue safe.
__global__ void k_agg(const float* __restrict__ bias, int do_stats) {
    int node = (blockIdx.x * blockDim.x + threadIdx.x) >> 5;
    int lane = threadIdx.x & 31;

    int   off = g_off[node];                 // multiple of 16
    int   nb  = (g_deg[node] + 16) >> 4;     // ceil((deg+1)/16)
    float di  = g_dis[node];
    float ax = 0.f, ay = 0.f;

    const int4* e4 = g_edge4 + (off >> 1);
    const unsigned* feat = g_xwh;

    for (int b = 0; b < nb; b++, e4 += 8) {
        int4 eb[8];
#pragma unroll
        for (int j = 0; j < 8; j++) eb[j] = e4[j];    // uniform LDG.128 broadcast

        unsigned hv[16]; float ww[16];
#pragma unroll
        for (int j = 0; j < 16; j++) {
            int4 p  = eb[j >> 1];
            int rs  = (j & 1) ? p.z : p.x;            // src*32 (pad: 0)
            int wb  = (j & 1) ? p.w : p.y;            // weight bits (pad: 0.0)
            ww[j] = __int_as_float(wb);
            hv[j] = feat[rs + lane];                  // unconditional gather
        }
#pragma unroll
        for (int j = 0; j < 16; j++) {
            float2 v = __half22float2(*(__half2*)&hv[j]);
            ax += ww[j] * v.x;
            ay += ww[j] * v.y;
        }
    }

    float2 bb = *(const float2*)(bias + 2 * lane);
    float o0 = fmaxf(ax * di + bb.x, 0.f);
    float o1 = fmaxf(ay * di + bb.y, 0.f);
    *(float2*)(g_x + (size_t)node * C + 2 * lane) = make_float2(o0, o1);

    if (do_stats) {
        float s  = o0 + o1;
        float s2 = o0 * o0 + o1 * o1;
#pragma unroll
        for (int o = 16; o; o >>= 1) {
            s  += __shfl_down_sync(0xffffffffu, s,  o);
            s2 += __shfl_down_sync(0xffffffffu, s2, o);
        }
        __shared__ float ss[8], ss2[8];
        int w = threadIdx.x >> 5;
        if (lane == 0) { ss[w] = s; ss2[w] = s2; }
        __syncthreads();
        if (w == 0 && lane < 8) {
            s  = ss[lane];
            s2 = ss2[lane];
#pragma unroll
            for (int o = 4; o; o >>= 1) {
                s  += __shfl_down_sync(0x000000ffu, s,  o);
                s2 += __shfl_down_sync(0x000000ffu, s2, o);
            }
            if (lane == 0) {
                atomicAdd(&g_stats[0], (double)s);
                atomicAdd(&g_stats[1], (double)s2);
            }
        }
    }
}

// ---------------- graph layernorm (float4) ----------------
__global__ void k_ln(const float* __restrict__ lnw,
                     const float* __restrict__ lnb,
                     float* __restrict__ out) {
    const int M4 = NN * C / 4;
    double mean = g_stats[0] / (double)(NN * C);
    double var  = g_stats[1] / (double)(NN * C) - mean * mean;
    float scale = (float)(1.0 / sqrt(var + 1e-5)) * lnw[0];
    float mu    = (float)mean;
    float shb   = lnb[0];
    const float4* xi = (const float4*)g_x;
    float4* xo = (float4*)out;
    int stride = gridDim.x * blockDim.x;
    for (int i = blockIdx.x * blockDim.x + threadIdx.x; i < M4; i += stride) {
        float4 v = xi[i];
        v.x = (v.x - mu) * scale + shb;
        v.y = (v.y - mu) * scale + shb;
        v.z = (v.z - mu) * scale + shb;
        v.w = (v.w - mu) * scale + shb;
        xo[i] = v;
    }
}

extern "C" void kernel_launch(void* const* d_in, const int* in_sizes, int n_in,
                              void* d_out, int out_size) {
    const float* X    = (const float*)d_in[0];
    const int*   edges= (const int*)d_in[1];   // int32 (JAX x64 disabled)
    const float* W1   = (const float*)d_in[2];
    const float* b1   = (const float*)d_in[3];
    const float* W2   = (const float*)d_in[4];
    const float* b2   = (const float*)d_in[5];
    const float* lnw  = (const float*)d_in[6];
    const float* lnb  = (const float*)d_in[7];
    float* out = (float*)d_out;

    const int* srcp = edges;        // edges[0]
    const int* dstp = edges + EE;   // edges[1]

    const int agg_grid  = (NN * 32) / 256;                 // exactly 12500
    const int gemm_grid = ((NN / RPW) * 32) / 256;         // exactly 3125

    k_clear<<<(ECAP_4 + 255) / 256, 256>>>();
    k_hist<<<2048, 256>>>(dstp);
    k_scan_a<<<SCAN_NB, SCAN_B>>>();
    k_gemm<<<gemm_grid, 256>>>(X, W1, 0);      // slot 3: ncu-sampled (FFMA2 control)
    k_scan_b<<<1, 256>>>();
    k_scan_c<<<(NN + 255) / 256, 256>>>();
    k_fill<<<2048, 256>>>(srcp, dstp);

    // layer 1 aggregation
    k_agg<<<agg_grid, 256>>>(b1, 0);
    // layer 2 (residual mix GW*h+(1-GW)*h == h); agg2 fuses global stats
    k_gemm<<<gemm_grid, 256>>>(X, W2, 1);
    k_agg<<<agg_grid, 256>>>(b2, 1);

    // graph layernorm
    k_ln<<<4096, 256>>>(lnw, lnb, out);
}

// round 10
// speedup vs baseline: 1.4263x; 1.1074x over previous
#include <cuda_runtime.h>
#include <cuda_fp16.h>

#define NN 100000
#define EE 1600000
#define C  64

#define SCAN_B 512
#define SCAN_NB ((NN + SCAN_B - 1) / SCAN_B)   // 196

// padded CSR: every node segment rounded up to multiple of 16 edges
#define ECAP_E (EE + 16 * NN)
#define ECAP_4 (ECAP_E / 2)

#define RPW 4
#define GEMM_BLKS ((NN / RPW) * 32 / 256)      // 3125
#define HIST_BLKS 2048

// ---- scratch (device globals) ----
__device__ int       g_deg[NN];
__device__ int       g_off[NN];
__device__ int       g_cur[NN];
__device__ float     g_dis[NN];
__device__ int       g_bsum[SCAN_NB];
__device__ int       g_boff[SCAN_NB];
__device__ int4      g_edge4[ECAP_4];          // (src*32, w_bits) pairs
__device__ unsigned  g_xwh[(size_t)NN * 32];   // X@W, half2-packed
__device__ float     g_x [(size_t)NN * C];
__device__ double    g_stats[2];

// ---------------- clear: edge pad slots, histogram, stats ----------------
__global__ void k_clear() {
    int i = blockIdx.x * blockDim.x + threadIdx.x;
    int stride = gridDim.x * blockDim.x;
    for (int j = i; j < ECAP_4; j += stride)
        g_edge4[j] = make_int4(0, 0, 0, 0);
    if (i < NN) g_deg[i] = 0;
    if (i < 2)  g_stats[i] = 0.0;
}

// ---------------- gemm device body (R8-verified form) ----------------
__device__ __forceinline__ void gemm_body(const float* __restrict__ Xin,
                                          const float* __restrict__ W,
                                          int gblk) {
    __shared__ float2 Wp[C][32];    // (W[k][2l], W[k][2l+1])
    __shared__ float4 Xs[8][C];     // Xs[warp][k] = 4 rows' col k
    for (int i = threadIdx.x; i < C * 32; i += blockDim.x) {
        int k = i >> 5, l = i & 31;
        Wp[k][l] = make_float2(W[k * C + 2 * l], W[k * C + 2 * l + 1]);
    }

    int warp = (gblk * 256 + threadIdx.x) >> 5;   // < NN/RPW exactly
    int w    = threadIdx.x >> 5;
    int lane = threadIdx.x & 31;
    int r0 = warp * RPW;

    {
        float2 xv[RPW];
#pragma unroll
        for (int i = 0; i < RPW; i++)
            xv[i] = *(const float2*)(Xin + (size_t)(r0 + i) * C + 2 * lane);
        Xs[w][2 * lane]     = make_float4(xv[0].x, xv[1].x, xv[2].x, xv[3].x);
        Xs[w][2 * lane + 1] = make_float4(xv[0].y, xv[1].y, xv[2].y, xv[3].y);
    }
    __syncthreads();

    float a0[RPW] = {0.f, 0.f, 0.f, 0.f};
    float a1[RPW] = {0.f, 0.f, 0.f, 0.f};
#pragma unroll
    for (int k = 0; k < C; k++) {
        float4 xk = Xs[w][k];          // LDS.128 broadcast
        float2 wv = Wp[k][lane];       // LDS.64 conflict-free
        a0[0] += xk.x * wv.x;  a1[0] += xk.x * wv.y;
        a0[1] += xk.y * wv.x;  a1[1] += xk.y * wv.y;
        a0[2] += xk.z * wv.x;  a1[2] += xk.z * wv.y;
        a0[3] += xk.w * wv.x;  a1[3] += xk.w * wv.y;
    }
#pragma unroll
    for (int i = 0; i < RPW; i++) {
        __half2 h = __float22half2_rn(make_float2(a0[i], a1[i]));
        g_xwh[(size_t)(r0 + i) * 32 + lane] = *(unsigned*)&h;
    }
}

// ---------------- merged: gemm layer-1 (blocks < GEMM_BLKS) + dst histogram ----------------
__global__ void k_gemm_hist(const float* __restrict__ X,
                            const float* __restrict__ W,
                            const int* __restrict__ dst) {
    if (blockIdx.x < GEMM_BLKS) {
        gemm_body(X, W, blockIdx.x);
    } else {
        int tid = (blockIdx.x - GEMM_BLKS) * blockDim.x + threadIdx.x;
        int stride = HIST_BLKS * blockDim.x;
        for (int e = tid; e < EE; e += stride)
            atomicAdd(&g_deg[dst[e]], 1);
    }
}

// ---------------- gemm layer-2 (reads g_x) ----------------
__global__ void k_gemm2(const float* __restrict__ W) {
    gemm_body(g_x, W, blockIdx.x);
}

// ---------------- scan A: block-local exclusive scan of pad16(deg+1) ----------------
__global__ void k_scan_a() {
    __shared__ int sh[SCAN_B];
    int t = threadIdx.x;
    int i = blockIdx.x * SCAN_B + t;
    int v = (i < NN) ? ((g_deg[i] + 16) & ~15) : 0;
    sh[t] = v;
    __syncthreads();
    int acc = v;
#pragma unroll
    for (int d = 1; d < SCAN_B; d <<= 1) {
        int u = (t >= d) ? sh[t - d] : 0;
        __syncthreads();
        acc += u;
        sh[t] = acc;
        __syncthreads();
    }
    if (i < NN) g_off[i] = acc - v;
    if (t == SCAN_B - 1) g_bsum[blockIdx.x] = acc;
}

// ---------------- scan B ----------------
__global__ void k_scan_b() {
    __shared__ int sh[256];
    int t = threadIdx.x;
    int v = (t < SCAN_NB) ? g_bsum[t] : 0;
    sh[t] = v;
    __syncthreads();
    int acc = v;
#pragma unroll
    for (int d = 1; d < 256; d <<= 1) {
        int u = (t >= d) ? sh[t - d] : 0;
        __syncthreads();
        acc += u;
        sh[t] = acc;
        __syncthreads();
    }
    if (t < SCAN_NB) g_boff[t] = acc - v;
}

// ---------------- scan C ----------------
__global__ void k_scan_c() {
    int i = blockIdx.x * blockDim.x + threadIdx.x;
    if (i >= NN) return;
    int off = g_off[i] + g_boff[i / SCAN_B];
    g_off[i] = off;
    g_cur[i] = off;
    g_dis[i] = rsqrtf((float)(g_deg[i] + 1));
}

// ---------------- fill CSR (edges + self loops): (src*32, w_bits) ----------------
__global__ void k_fill(const int* __restrict__ src,
                       const int* __restrict__ dst) {
    int stride = gridDim.x * blockDim.x;
    const int tot = EE + NN;
    int2* ge = (int2*)g_edge4;
    for (int e = blockIdx.x * blockDim.x + threadIdx.x; e < tot; e += stride) {
        int s, d;
        if (e < EE) { s = src[e]; d = dst[e]; }
        else        { s = e - EE; d = s; }
        int pos = atomicAdd(&g_cur[d], 1);
        float w = g_dis[s];
        ge[pos] = make_int2(s * 32, __float_as_int(w));
    }
}

// ---------------- aggregate: warp/node, padded unconditional 16-edge batches ----------------
__global__ void k_agg(const float* __restrict__ bias, int do_stats) {
    int node = (blockIdx.x * blockDim.x + threadIdx.x) >> 5;
    int lane = threadIdx.x & 31;

    int   off = g_off[node];                 // multiple of 16
    int   nb  = (g_deg[node] + 16) >> 4;     // ceil((deg+1)/16)
    float di  = g_dis[node];
    float ax = 0.f, ay = 0.f;

    const int4* e4 = g_edge4 + (off >> 1);
    const unsigned* feat = g_xwh;

    for (int b = 0; b < nb; b++, e4 += 8) {
        int4 eb[8];
#pragma unroll
        for (int j = 0; j < 8; j++) eb[j] = e4[j];    // uniform LDG.128 broadcast

        unsigned hv[16]; float ww[16];
#pragma unroll
        for (int j = 0; j < 16; j++) {
            int4 p  = eb[j >> 1];
            int rs  = (j & 1) ? p.z : p.x;            // src*32 (pad: 0)
            int wb  = (j & 1) ? p.w : p.y;            // weight bits (pad: 0.0)
            ww[j] = __int_as_float(wb);
            hv[j] = feat[rs + lane];
        }
#pragma unroll
        for (int j = 0; j < 16; j++) {
            float2 v = __half22float2(*(__half2*)&hv[j]);
            ax += ww[j] * v.x;
            ay += ww[j] * v.y;
        }
    }

    float2 bb = *(const float2*)(bias + 2 * lane);
    float o0 = fmaxf(ax * di + bb.x, 0.f);
    float o1 = fmaxf(ay * di + bb.y, 0.f);
    *(float2*)(g_x + (size_t)node * C + 2 * lane) = make_float2(o0, o1);

    if (do_stats) {
        float s  = o0 + o1;
        float s2 = o0 * o0 + o1 * o1;
#pragma unroll
        for (int o = 16; o; o >>= 1) {
            s  += __shfl_down_sync(0xffffffffu, s,  o);
            s2 += __shfl_down_sync(0xffffffffu, s2, o);
        }
        __shared__ float ss[8], ss2[8];
        int w = threadIdx.x >> 5;
        if (lane == 0) { ss[w] = s; ss2[w] = s2; }
        __syncthreads();
        if (w == 0 && lane < 8) {
            s  = ss[lane];
            s2 = ss2[lane];
#pragma unroll
            for (int o = 4; o; o >>= 1) {
                s  += __shfl_down_sync(0x000000ffu, s,  o);
                s2 += __shfl_down_sync(0x000000ffu, s2, o);
            }
            if (lane == 0) {
                atomicAdd(&g_stats[0], (double)s);
                atomicAdd(&g_stats[1], (double)s2);
            }
        }
    }
}

// ---------------- graph layernorm (float4) ----------------
__global__ void k_ln(const float* __restrict__ lnw,
                     const float* __restrict__ lnb,
                     float* __restrict__ out) {
    const int M4 = NN * C / 4;
    double mean = g_stats[0] / (double)(NN * C);
    double var  = g_stats[1] / (double)(NN * C) - mean * mean;
    float scale = (float)(1.0 / sqrt(var + 1e-5)) * lnw[0];
    float mu    = (float)mean;
    float shb   = lnb[0];
    const float4* xi = (const float4*)g_x;
    float4* xo = (float4*)out;
    int stride = gridDim.x * blockDim.x;
    for (int i = blockIdx.x * blockDim.x + threadIdx.x; i < M4; i += stride) {
        float4 v = xi[i];
        v.x = (v.x - mu) * scale + shb;
        v.y = (v.y - mu) * scale + shb;
        v.z = (v.z - mu) * scale + shb;
        v.w = (v.w - mu) * scale + shb;
        xo[i] = v;
    }
}

extern "C" void kernel_launch(void* const* d_in, const int* in_sizes, int n_in,
                              void* d_out, int out_size) {
    const float* X    = (const float*)d_in[0];
    const int*   edges= (const int*)d_in[1];   // int32 (JAX x64 disabled)
    const float* W1   = (const float*)d_in[2];
    const float* b1   = (const float*)d_in[3];
    const float* W2   = (const float*)d_in[4];
    const float* b2   = (const float*)d_in[5];
    const float* lnw  = (const float*)d_in[6];
    const float* lnb  = (const float*)d_in[7];
    float* out = (float*)d_out;

    const int* srcp = edges;        // edges[0]
    const int* dstp = edges + EE;   // edges[1]

    const int agg_grid = (NN * 32) / 256;                  // exactly 12500

    k_clear<<<(ECAP_4 + 255) / 256, 256>>>();
    // merged: gemm layer-1 (independent) overlaps dst histogram
    k_gemm_hist<<<GEMM_BLKS + HIST_BLKS, 256>>>(X, W1, dstp);
    k_scan_a<<<SCAN_NB, SCAN_B>>>();
    k_scan_b<<<1, 256>>>();
    k_scan_c<<<(NN + 255) / 256, 256>>>();
    k_fill<<<2048, 256>>>(srcp, dstp);

    // layer 1 aggregation
    k_agg<<<agg_grid, 256>>>(b1, 0);
    // layer 2 (residual mix GW*h+(1-GW)*h == h); agg2 fuses global stats
    k_gemm2<<<GEMM_BLKS, 256>>>(W2);
    k_agg<<<agg_grid, 256>>>(b2, 1);

    // graph layernorm
    k_ln<<<4096, 256>>>(lnw, lnb, out);
}